// round 1
// baseline (speedup 1.0000x reference)
#include <cuda_runtime.h>
#include <cuda_bf16.h>
#include <cstdint>

#define NUM_USERS 100000
#define NUM_ITEMS 100000
#define NUM_NODES (NUM_USERS + NUM_ITEMS)
#define EMB_DIM 64
#define NUM_EDGES 4000000
#define BATCH 4096
// EMB_DIM floats = 16 float4 chunks per node
#define CHUNKS 16

// ---- scratch (device globals: allocation-free) ----
__device__ float4 g_h1[NUM_NODES * CHUNKS];          // 51.2 MB
__device__ float4 g_h2[NUM_NODES * CHUNKS];          // 51.2 MB (only flagged rows valid)
__device__ unsigned char g_flag[NUM_NODES];          // 200 KB

__device__ __forceinline__ void red_add_v4(float4* addr, float4 v) {
    asm volatile("red.global.add.v4.f32 [%0], {%1, %2, %3, %4};"
                 :: "l"(addr), "f"(v.x), "f"(v.y), "f"(v.z), "f"(v.w)
                 : "memory");
}

// ---- K0a: zero h1 + flags ----
#define H1_WORDS (NUM_NODES * CHUNKS)                 // 3,200,000 float4
#define FLAG_WORDS (NUM_NODES / 16)                   // 12,500 uint4 (200000 bytes)
__global__ void k_zero(void) {
    int i = blockIdx.x * blockDim.x + threadIdx.x;
    if (i < H1_WORDS) {
        g_h1[i] = make_float4(0.f, 0.f, 0.f, 0.f);
    } else if (i < H1_WORDS + FLAG_WORDS) {
        ((uint4*)g_flag)[i - H1_WORDS] = make_uint4(0u, 0u, 0u, 0u);
    }
}

// ---- K0b: set flags for needed rows + zero those h2 rows ----
__global__ void k_flag(const int* __restrict__ user,
                       const int* __restrict__ pos,
                       const int* __restrict__ neg) {
    int t = blockIdx.x * blockDim.x + threadIdx.x;   // 3*BATCH*16 threads
    int g = t >> 4;          // group index 0..3*BATCH-1
    int c = t & 15;          // chunk
    if (g >= 3 * BATCH) return;
    int node;
    if (g < BATCH)            node = user[g];
    else if (g < 2 * BATCH)   node = NUM_USERS + pos[g - BATCH];
    else                      node = NUM_USERS + neg[g - 2 * BATCH];
    if (c == 0) g_flag[node] = 1;
    g_h2[node * CHUNKS + c] = make_float4(0.f, 0.f, 0.f, 0.f);
}

// ---- K1: full SPMM layer 1: h1[row] += val * all_emb[col] ----
__global__ void k_spmm1(const int*   __restrict__ edge_row,
                        const int*   __restrict__ edge_col,
                        const float* __restrict__ edge_val,
                        const float4* __restrict__ user_emb,   // as float4
                        const float4* __restrict__ item_emb) {
    int t = blockIdx.x * blockDim.x + threadIdx.x;
    int e = t >> 4;
    int c = t & 15;
    if (e >= NUM_EDGES) return;
    int row = __ldg(edge_row + e);
    int col = __ldg(edge_col + e);
    float v = __ldg(edge_val + e);
    const float4* src = (col < NUM_USERS) ? (user_emb + (size_t)col * CHUNKS)
                                          : (item_emb + (size_t)(col - NUM_USERS) * CHUNKS);
    float4 x = __ldg(src + c);
    float4 m = make_float4(v * x.x, v * x.y, v * x.z, v * x.w);
    red_add_v4(&g_h1[(size_t)row * CHUNKS + c], m);
}

// ---- K2: filtered SPMM layer 2: h2[row] += val * h1[col], only flagged rows ----
__global__ void k_spmm2(const int*   __restrict__ edge_row,
                        const int*   __restrict__ edge_col,
                        const float* __restrict__ edge_val) {
    int t = blockIdx.x * blockDim.x + threadIdx.x;
    int e = t >> 4;
    int c = t & 15;
    if (e >= NUM_EDGES) return;
    int row = __ldg(edge_row + e);
    if (!g_flag[row]) return;
    int col = __ldg(edge_col + e);
    float v = __ldg(edge_val + e);
    float4 x = __ldg(&g_h1[(size_t)col * CHUNKS + c]);
    float4 m = make_float4(v * x.x, v * x.y, v * x.z, v * x.w);
    red_add_v4(&g_h2[(size_t)row * CHUNKS + c], m);
}

// ---- K3: gather acc at batch nodes, dot, write scores ----
// acc = (emb + h1 + h2); score = dot(acc_u, acc_i) / 9
__global__ void k_score(const int* __restrict__ user,
                        const int* __restrict__ pos,
                        const int* __restrict__ neg,
                        const float2* __restrict__ user_emb2,
                        const float2* __restrict__ item_emb2,
                        float* __restrict__ out) {
    int w = (blockIdx.x * blockDim.x + threadIdx.x) >> 5;  // warp id = batch idx
    int lane = threadIdx.x & 31;
    if (w >= BATCH) return;
    int nu = user[w];
    int np = NUM_USERS + pos[w];
    int nn = NUM_USERS + neg[w];

    const float2* h1 = (const float2*)g_h1;
    const float2* h2 = (const float2*)g_h2;
    const int L = EMB_DIM / 2;  // 32 float2 per node

    float2 ue = user_emb2[(size_t)nu * L + lane];
    float2 u1 = h1[(size_t)nu * L + lane];
    float2 u2 = h2[(size_t)nu * L + lane];
    float ux = ue.x + u1.x + u2.x;
    float uy = ue.y + u1.y + u2.y;

    float2 pe = item_emb2[(size_t)(np - NUM_USERS) * L + lane];
    float2 p1 = h1[(size_t)np * L + lane];
    float2 p2 = h2[(size_t)np * L + lane];
    float px = pe.x + p1.x + p2.x;
    float py = pe.y + p1.y + p2.y;

    float2 ne = item_emb2[(size_t)(nn - NUM_USERS) * L + lane];
    float2 n1 = h1[(size_t)nn * L + lane];
    float2 n2 = h2[(size_t)nn * L + lane];
    float nx = ne.x + n1.x + n2.x;
    float ny = ne.y + n1.y + n2.y;

    float sp = ux * px + uy * py;
    float sn = ux * nx + uy * ny;
    #pragma unroll
    for (int off = 16; off > 0; off >>= 1) {
        sp += __shfl_xor_sync(0xFFFFFFFFu, sp, off);
        sn += __shfl_xor_sync(0xFFFFFFFFu, sn, off);
    }
    if (lane == 0) {
        const float inv9 = 1.0f / 9.0f;
        out[w]         = sp * inv9;
        out[BATCH + w] = sn * inv9;
    }
}

extern "C" void kernel_launch(void* const* d_in, const int* in_sizes, int n_in,
                              void* d_out, int out_size) {
    const int*   user     = (const int*)  d_in[0];
    const int*   pos      = (const int*)  d_in[1];
    const int*   neg      = (const int*)  d_in[2];
    const int*   edge_row = (const int*)  d_in[3];
    const int*   edge_col = (const int*)  d_in[4];
    const float* edge_val = (const float*)d_in[5];
    const float* user_emb = (const float*)d_in[6];
    const float* item_emb = (const float*)d_in[7];
    float* out = (float*)d_out;

    // K0a: zero h1 + flags
    {
        int total = H1_WORDS + FLAG_WORDS;
        int blocks = (total + 255) / 256;
        k_zero<<<blocks, 256>>>();
    }
    // K0b: flags + zero needed h2 rows
    {
        int total = 3 * BATCH * CHUNKS;
        int blocks = (total + 255) / 256;
        k_flag<<<blocks, 256>>>(user, pos, neg);
    }
    // K1: SPMM layer 1 (full)
    {
        long long total = (long long)NUM_EDGES * CHUNKS;
        int blocks = (int)((total + 255) / 256);
        k_spmm1<<<blocks, 256>>>(edge_row, edge_col, edge_val,
                                 (const float4*)user_emb, (const float4*)item_emb);
    }
    // K2: SPMM layer 2 (row-filtered)
    {
        long long total = (long long)NUM_EDGES * CHUNKS;
        int blocks = (int)((total + 255) / 256);
        k_spmm2<<<blocks, 256>>>(edge_row, edge_col, edge_val);
    }
    // K3: scores
    {
        int threads = 256;
        int blocks = (BATCH * 32 + threads - 1) / threads;
        k_score<<<blocks, threads>>>(user, pos, neg,
                                     (const float2*)user_emb, (const float2*)item_emb,
                                     out);
    }
}

// round 2
// speedup vs baseline: 1.5714x; 1.5714x over previous
#include <cuda_runtime.h>
#include <cuda_bf16.h>
#include <cstdint>

#define NUM_USERS 100000
#define NUM_ITEMS 100000
#define NUM_NODES (NUM_USERS + NUM_ITEMS)
#define EMB_DIM 64
#define NUM_EDGES 4000000
#define BATCH 4096
#define CHUNKS 16   // 16 float4 per node row

// ---- scratch (device globals: allocation-free) ----
__device__ float4 g_h1[NUM_NODES * CHUNKS];          // 51.2 MB
__device__ float4 g_h2[NUM_NODES * CHUNKS];          // 51.2 MB (only flagged rows valid)
__device__ unsigned char g_flag[NUM_NODES];          // 200 KB
__device__ int g_edge_list[NUM_EDGES];               // compacted edge ids (worst case)
__device__ int g_edge_count;

__device__ __forceinline__ void red_add_v4(float4* addr, float4 v) {
    asm volatile("red.global.add.v4.f32 [%0], {%1, %2, %3, %4};"
                 :: "l"(addr), "f"(v.x), "f"(v.y), "f"(v.z), "f"(v.w)
                 : "memory");
}

// ---- K0a: zero h1 + flags + counter ----
#define H1_WORDS (NUM_NODES * CHUNKS)                 // 3,200,000 float4
#define FLAG_WORDS (NUM_NODES / 16)                   // 12,500 uint4
__global__ void k_zero(void) {
    int i = blockIdx.x * blockDim.x + threadIdx.x;
    if (i == 0) g_edge_count = 0;
    if (i < H1_WORDS) {
        g_h1[i] = make_float4(0.f, 0.f, 0.f, 0.f);
    } else if (i < H1_WORDS + FLAG_WORDS) {
        ((uint4*)g_flag)[i - H1_WORDS] = make_uint4(0u, 0u, 0u, 0u);
    }
}

// ---- K0b: set flags for needed rows + zero those h2 rows ----
__global__ void k_flag(const int* __restrict__ user,
                       const int* __restrict__ pos,
                       const int* __restrict__ neg) {
    int t = blockIdx.x * blockDim.x + threadIdx.x;   // 3*BATCH*16 threads
    int g = t >> 4;
    int c = t & 15;
    if (g >= 3 * BATCH) return;
    int node;
    if (g < BATCH)            node = user[g];
    else if (g < 2 * BATCH)   node = NUM_USERS + pos[g - BATCH];
    else                      node = NUM_USERS + neg[g - 2 * BATCH];
    if (c == 0) g_flag[node] = 1;
    g_h2[node * CHUNKS + c] = make_float4(0.f, 0.f, 0.f, 0.f);
}

// ---- K1: full SPMM layer 1: h1[row] += val * all_emb[col] ----
// Each thread handles 2 independent (edge, chunk) items for MLP=2.
#define SPMM1_ITEMS (NUM_EDGES * CHUNKS)     // 64M
#define SPMM1_HALF  (SPMM1_ITEMS / 2)        // 32M
__global__ void k_spmm1(const int*   __restrict__ edge_row,
                        const int*   __restrict__ edge_col,
                        const float* __restrict__ edge_val,
                        const float4* __restrict__ user_emb,
                        const float4* __restrict__ item_emb) {
    int t = blockIdx.x * blockDim.x + threadIdx.x;
    if (t >= SPMM1_HALF) return;

    int e0 = t >> 4;                 // edges [0, 2M)
    int c0 = t & 15;
    int e1 = e0 + (NUM_EDGES / 2);   // edges [2M, 4M)
    int c1 = c0;

    // issue both edge-metadata loads up front
    int   row0 = __ldg(edge_row + e0);
    int   row1 = __ldg(edge_row + e1);
    int   col0 = __ldg(edge_col + e0);
    int   col1 = __ldg(edge_col + e1);
    float v0   = __ldg(edge_val + e0);
    float v1   = __ldg(edge_val + e1);

    const float4* src0 = (col0 < NUM_USERS) ? (user_emb + (size_t)col0 * CHUNKS)
                                            : (item_emb + (size_t)(col0 - NUM_USERS) * CHUNKS);
    const float4* src1 = (col1 < NUM_USERS) ? (user_emb + (size_t)col1 * CHUNKS)
                                            : (item_emb + (size_t)(col1 - NUM_USERS) * CHUNKS);
    float4 x0 = __ldg(src0 + c0);
    float4 x1 = __ldg(src1 + c1);

    float4 m0 = make_float4(v0 * x0.x, v0 * x0.y, v0 * x0.z, v0 * x0.w);
    float4 m1 = make_float4(v1 * x1.x, v1 * x1.y, v1 * x1.z, v1 * x1.w);
    red_add_v4(&g_h1[(size_t)row0 * CHUNKS + c0], m0);
    red_add_v4(&g_h1[(size_t)row1 * CHUNKS + c1], m1);
}

// ---- K2a: compact edges whose row is flagged ----
// 1 thread per 4 edges, int4 loads, warp-aggregated append.
__global__ void k_compact(const int* __restrict__ edge_row) {
    int t = blockIdx.x * blockDim.x + threadIdx.x;
    int base = t * 4;
    if (base >= NUM_EDGES) return;
    int4 rows = __ldg((const int4*)(edge_row) + t);

    #pragma unroll
    for (int j = 0; j < 4; j++) {
        int e = base + j;
        int r = (j == 0) ? rows.x : (j == 1) ? rows.y : (j == 2) ? rows.z : rows.w;
        bool keep = (g_flag[r] != 0);
        unsigned mask = __ballot_sync(0xFFFFFFFFu, keep);
        if (mask) {
            int lane = threadIdx.x & 31;
            int leader = __ffs(mask) - 1;
            int pos_in_warp = __popc(mask & ((1u << lane) - 1));
            int warp_base;
            if (lane == leader) warp_base = atomicAdd(&g_edge_count, __popc(mask));
            warp_base = __shfl_sync(0xFFFFFFFFu, warp_base, leader);
            if (keep) g_edge_list[warp_base + pos_in_warp] = e;
        }
    }
}

// ---- K2b: filtered SPMM layer 2 over compacted edges ----
__global__ void k_spmm2(const int*   __restrict__ edge_row,
                        const int*   __restrict__ edge_col,
                        const float* __restrict__ edge_val) {
    int n = g_edge_count;                 // finalized by k_compact (separate launch)
    long long total = (long long)n * CHUNKS;
    long long stride = (long long)gridDim.x * blockDim.x;
    for (long long t = blockIdx.x * (long long)blockDim.x + threadIdx.x;
         t < total; t += stride) {
        int idx = (int)(t >> 4);
        int c = (int)(t & 15);
        int e = g_edge_list[idx];
        int row = __ldg(edge_row + e);
        int col = __ldg(edge_col + e);
        float v = __ldg(edge_val + e);
        float4 x = __ldg(&g_h1[(size_t)col * CHUNKS + c]);
        float4 m = make_float4(v * x.x, v * x.y, v * x.z, v * x.w);
        red_add_v4(&g_h2[(size_t)row * CHUNKS + c], m);
    }
}

// ---- K3: gather acc at batch nodes, dot, write scores ----
__global__ void k_score(const int* __restrict__ user,
                        const int* __restrict__ pos,
                        const int* __restrict__ neg,
                        const float2* __restrict__ user_emb2,
                        const float2* __restrict__ item_emb2,
                        float* __restrict__ out) {
    int w = (blockIdx.x * blockDim.x + threadIdx.x) >> 5;
    int lane = threadIdx.x & 31;
    if (w >= BATCH) return;
    int nu = user[w];
    int np = NUM_USERS + pos[w];
    int nn = NUM_USERS + neg[w];

    const float2* h1 = (const float2*)g_h1;
    const float2* h2 = (const float2*)g_h2;
    const int L = EMB_DIM / 2;

    float2 ue = user_emb2[(size_t)nu * L + lane];
    float2 u1 = h1[(size_t)nu * L + lane];
    float2 u2 = h2[(size_t)nu * L + lane];
    float ux = ue.x + u1.x + u2.x;
    float uy = ue.y + u1.y + u2.y;

    float2 pe = item_emb2[(size_t)(np - NUM_USERS) * L + lane];
    float2 p1 = h1[(size_t)np * L + lane];
    float2 p2 = h2[(size_t)np * L + lane];
    float px = pe.x + p1.x + p2.x;
    float py = pe.y + p1.y + p2.y;

    float2 ne = item_emb2[(size_t)(nn - NUM_USERS) * L + lane];
    float2 n1 = h1[(size_t)nn * L + lane];
    float2 n2 = h2[(size_t)nn * L + lane];
    float nx = ne.x + n1.x + n2.x;
    float ny = ne.y + n1.y + n2.y;

    float sp = ux * px + uy * py;
    float sn = ux * nx + uy * ny;
    #pragma unroll
    for (int off = 16; off > 0; off >>= 1) {
        sp += __shfl_xor_sync(0xFFFFFFFFu, sp, off);
        sn += __shfl_xor_sync(0xFFFFFFFFu, sn, off);
    }
    if (lane == 0) {
        const float inv9 = 1.0f / 9.0f;
        out[w]         = sp * inv9;
        out[BATCH + w] = sn * inv9;
    }
}

extern "C" void kernel_launch(void* const* d_in, const int* in_sizes, int n_in,
                              void* d_out, int out_size) {
    const int*   user     = (const int*)  d_in[0];
    const int*   pos      = (const int*)  d_in[1];
    const int*   neg      = (const int*)  d_in[2];
    const int*   edge_row = (const int*)  d_in[3];
    const int*   edge_col = (const int*)  d_in[4];
    const float* edge_val = (const float*)d_in[5];
    const float* user_emb = (const float*)d_in[6];
    const float* item_emb = (const float*)d_in[7];
    float* out = (float*)d_out;

    // K0a: zero h1 + flags + counter
    {
        int total = H1_WORDS + FLAG_WORDS;
        k_zero<<<(total + 255) / 256, 256>>>();
    }
    // K0b: flags + zero needed h2 rows
    {
        int total = 3 * BATCH * CHUNKS;
        k_flag<<<(total + 255) / 256, 256>>>(user, pos, neg);
    }
    // K1: SPMM layer 1 (full), 2 items per thread
    {
        int blocks = (SPMM1_HALF + 255) / 256;
        k_spmm1<<<blocks, 256>>>(edge_row, edge_col, edge_val,
                                 (const float4*)user_emb, (const float4*)item_emb);
    }
    // K2a: compact edges with flagged rows
    {
        int threads_needed = NUM_EDGES / 4;
        k_compact<<<(threads_needed + 255) / 256, 256>>>(edge_row);
    }
    // K2b: SPMM layer 2 over compacted edges (grid-stride)
    {
        k_spmm2<<<2048, 256>>>(edge_row, edge_col, edge_val);
    }
    // K3: scores
    {
        int threads = 256;
        int blocks = (BATCH * 32 + threads - 1) / threads;
        k_score<<<blocks, threads>>>(user, pos, neg,
                                     (const float2*)user_emb, (const float2*)item_emb,
                                     out);
    }
}

// round 3
// speedup vs baseline: 1.9352x; 1.2316x over previous
#include <cuda_runtime.h>
#include <cuda_bf16.h>
#include <cstdint>

#define NUM_USERS 100000
#define NUM_ITEMS 100000
#define NUM_NODES (NUM_USERS + NUM_ITEMS)
#define EMB_DIM 64
#define NUM_EDGES 4000000
#define BATCH 4096
#define CHUNKS 16   // 16 float4 per node row

// ---- scratch (device globals: allocation-free) ----
__device__ float4 g_h1[NUM_NODES * CHUNKS];          // 51.2 MB
__device__ float4 g_h2[NUM_NODES * CHUNKS];          // 51.2 MB (only flagged rows valid)
__device__ unsigned char g_flag[NUM_NODES];          // 200 KB
__device__ int g_edge_list[NUM_EDGES];               // compacted edge ids (worst case)
__device__ int g_edge_count;

__device__ __forceinline__ void red_add_v4(float4* addr, float4 v) {
    asm volatile("red.global.add.v4.f32 [%0], {%1, %2, %3, %4};"
                 :: "l"(addr), "f"(v.x), "f"(v.y), "f"(v.z), "f"(v.w)
                 : "memory");
}

// ---- K0a: zero h1 + flags + counter ----
#define H1_WORDS (NUM_NODES * CHUNKS)                 // 3,200,000 float4
#define FLAG_WORDS (NUM_NODES / 16)                   // 12,500 uint4
__global__ void k_zero(void) {
    int i = blockIdx.x * blockDim.x + threadIdx.x;
    if (i == 0) g_edge_count = 0;
    if (i < H1_WORDS) {
        g_h1[i] = make_float4(0.f, 0.f, 0.f, 0.f);
    } else if (i < H1_WORDS + FLAG_WORDS) {
        ((uint4*)g_flag)[i - H1_WORDS] = make_uint4(0u, 0u, 0u, 0u);
    }
}

// ---- K0b: set flags for needed rows + zero those h2 rows ----
__global__ void k_flag(const int* __restrict__ user,
                       const int* __restrict__ pos,
                       const int* __restrict__ neg) {
    int t = blockIdx.x * blockDim.x + threadIdx.x;   // 3*BATCH*16 threads
    int g = t >> 4;
    int c = t & 15;
    if (g >= 3 * BATCH) return;
    int node;
    if (g < BATCH)            node = user[g];
    else if (g < 2 * BATCH)   node = NUM_USERS + pos[g - BATCH];
    else                      node = NUM_USERS + neg[g - 2 * BATCH];
    if (c == 0) g_flag[node] = 1;
    g_h2[node * CHUNKS + c] = make_float4(0.f, 0.f, 0.f, 0.f);
}

// ---- K1: full SPMM layer 1: h1[row] += val * all_emb[col] ----
// Each thread handles 2 independent (edge, chunk) items for MLP=2.
#define SPMM1_ITEMS (NUM_EDGES * CHUNKS)     // 64M
#define SPMM1_HALF  (SPMM1_ITEMS / 2)        // 32M
__global__ void k_spmm1(const int*   __restrict__ edge_row,
                        const int*   __restrict__ edge_col,
                        const float* __restrict__ edge_val,
                        const float4* __restrict__ user_emb,
                        const float4* __restrict__ item_emb) {
    int t = blockIdx.x * blockDim.x + threadIdx.x;
    if (t >= SPMM1_HALF) return;

    int e0 = t >> 4;                 // edges [0, 2M)
    int c0 = t & 15;
    int e1 = e0 + (NUM_EDGES / 2);   // edges [2M, 4M)

    int   row0 = __ldg(edge_row + e0);
    int   row1 = __ldg(edge_row + e1);
    int   col0 = __ldg(edge_col + e0);
    int   col1 = __ldg(edge_col + e1);
    float v0   = __ldg(edge_val + e0);
    float v1   = __ldg(edge_val + e1);

    const float4* src0 = (col0 < NUM_USERS) ? (user_emb + (size_t)col0 * CHUNKS)
                                            : (item_emb + (size_t)(col0 - NUM_USERS) * CHUNKS);
    const float4* src1 = (col1 < NUM_USERS) ? (user_emb + (size_t)col1 * CHUNKS)
                                            : (item_emb + (size_t)(col1 - NUM_USERS) * CHUNKS);
    float4 x0 = __ldg(src0 + c0);
    float4 x1 = __ldg(src1 + c0);

    float4 m0 = make_float4(v0 * x0.x, v0 * x0.y, v0 * x0.z, v0 * x0.w);
    float4 m1 = make_float4(v1 * x1.x, v1 * x1.y, v1 * x1.z, v1 * x1.w);
    red_add_v4(&g_h1[(size_t)row0 * CHUNKS + c0], m0);
    red_add_v4(&g_h1[(size_t)row1 * CHUNKS + c0], m1);
}

// ---- K2a: compact edges whose row is flagged ----
// 1 thread/edge; warp ballot -> smem block counter -> ONE global atomic per block.
__global__ void k_compact(const int* __restrict__ edge_row) {
    __shared__ int s_cnt;
    __shared__ int s_base;
    __shared__ int s_warp_off[8];   // 256 threads = 8 warps

    int e = blockIdx.x * blockDim.x + threadIdx.x;
    int lane = threadIdx.x & 31;
    int warp = threadIdx.x >> 5;

    if (threadIdx.x == 0) s_cnt = 0;
    __syncthreads();

    bool keep = false;
    if (e < NUM_EDGES) {
        int r = __ldg(edge_row + e);
        keep = (g_flag[r] != 0);
    }
    unsigned mask = __ballot_sync(0xFFFFFFFFu, keep);
    int warp_total = __popc(mask);
    int rank = __popc(mask & ((1u << lane) - 1));

    if (lane == 0 && warp_total)
        s_warp_off[warp] = atomicAdd(&s_cnt, warp_total);
    __syncthreads();

    if (threadIdx.x == 0 && s_cnt)
        s_base = atomicAdd(&g_edge_count, s_cnt);
    __syncthreads();

    if (keep)
        g_edge_list[s_base + s_warp_off[warp] + rank] = e;
}

// ---- K2b: filtered SPMM layer 2 over compacted edges ----
__global__ void k_spmm2(const int*   __restrict__ edge_row,
                        const int*   __restrict__ edge_col,
                        const float* __restrict__ edge_val) {
    int n = g_edge_count;
    long long total = (long long)n * CHUNKS;
    long long stride = (long long)gridDim.x * blockDim.x;
    for (long long t = blockIdx.x * (long long)blockDim.x + threadIdx.x;
         t < total; t += stride) {
        int idx = (int)(t >> 4);
        int c = (int)(t & 15);
        int e = g_edge_list[idx];
        int row = __ldg(edge_row + e);
        int col = __ldg(edge_col + e);
        float v = __ldg(edge_val + e);
        float4 x = __ldg(&g_h1[(size_t)col * CHUNKS + c]);
        float4 m = make_float4(v * x.x, v * x.y, v * x.z, v * x.w);
        red_add_v4(&g_h2[(size_t)row * CHUNKS + c], m);
    }
}

// ---- K3: gather acc at batch nodes, dot, write scores ----
__global__ void k_score(const int* __restrict__ user,
                        const int* __restrict__ pos,
                        const int* __restrict__ neg,
                        const float2* __restrict__ user_emb2,
                        const float2* __restrict__ item_emb2,
                        float* __restrict__ out) {
    int w = (blockIdx.x * blockDim.x + threadIdx.x) >> 5;
    int lane = threadIdx.x & 31;
    if (w >= BATCH) return;
    int nu = user[w];
    int np = NUM_USERS + pos[w];
    int nn = NUM_USERS + neg[w];

    const float2* h1 = (const float2*)g_h1;
    const float2* h2 = (const float2*)g_h2;
    const int L = EMB_DIM / 2;

    float2 ue = user_emb2[(size_t)nu * L + lane];
    float2 u1 = h1[(size_t)nu * L + lane];
    float2 u2 = h2[(size_t)nu * L + lane];
    float ux = ue.x + u1.x + u2.x;
    float uy = ue.y + u1.y + u2.y;

    float2 pe = item_emb2[(size_t)(np - NUM_USERS) * L + lane];
    float2 p1 = h1[(size_t)np * L + lane];
    float2 p2 = h2[(size_t)np * L + lane];
    float px = pe.x + p1.x + p2.x;
    float py = pe.y + p1.y + p2.y;

    float2 ne = item_emb2[(size_t)(nn - NUM_USERS) * L + lane];
    float2 n1 = h1[(size_t)nn * L + lane];
    float2 n2 = h2[(size_t)nn * L + lane];
    float nx = ne.x + n1.x + n2.x;
    float ny = ne.y + n1.y + n2.y;

    float sp = ux * px + uy * py;
    float sn = ux * nx + uy * ny;
    #pragma unroll
    for (int off = 16; off > 0; off >>= 1) {
        sp += __shfl_xor_sync(0xFFFFFFFFu, sp, off);
        sn += __shfl_xor_sync(0xFFFFFFFFu, sn, off);
    }
    if (lane == 0) {
        const float inv9 = 1.0f / 9.0f;
        out[w]         = sp * inv9;
        out[BATCH + w] = sn * inv9;
    }
}

extern "C" void kernel_launch(void* const* d_in, const int* in_sizes, int n_in,
                              void* d_out, int out_size) {
    const int*   user     = (const int*)  d_in[0];
    const int*   pos      = (const int*)  d_in[1];
    const int*   neg      = (const int*)  d_in[2];
    const int*   edge_row = (const int*)  d_in[3];
    const int*   edge_col = (const int*)  d_in[4];
    const float* edge_val = (const float*)d_in[5];
    const float* user_emb = (const float*)d_in[6];
    const float* item_emb = (const float*)d_in[7];
    float* out = (float*)d_out;

    // K0a: zero h1 + flags + counter
    {
        int total = H1_WORDS + FLAG_WORDS;
        k_zero<<<(total + 255) / 256, 256>>>();
    }
    // K0b: flags + zero needed h2 rows
    {
        int total = 3 * BATCH * CHUNKS;
        k_flag<<<(total + 255) / 256, 256>>>(user, pos, neg);
    }
    // K1: SPMM layer 1 (full), 2 items per thread
    {
        int blocks = (SPMM1_HALF + 255) / 256;
        k_spmm1<<<blocks, 256>>>(edge_row, edge_col, edge_val,
                                 (const float4*)user_emb, (const float4*)item_emb);
    }
    // K2a: compact edges with flagged rows (1 thread/edge, block-aggregated atomic)
    {
        k_compact<<<(NUM_EDGES + 255) / 256, 256>>>(edge_row);
    }
    // K2b: SPMM layer 2 over compacted edges (grid-stride, deep grid)
    {
        k_spmm2<<<8192, 256>>>(edge_row, edge_col, edge_val);
    }
    // K3: scores
    {
        int threads = 256;
        int blocks = (BATCH * 32 + threads - 1) / threads;
        k_score<<<blocks, threads>>>(user, pos, neg,
                                     (const float2*)user_emb, (const float2*)item_emb,
                                     out);
    }
}

// round 5
// speedup vs baseline: 2.0324x; 1.0502x over previous
#include <cuda_runtime.h>
#include <cuda_bf16.h>
#include <cstdint>

#define NUM_USERS 100000
#define NUM_ITEMS 100000
#define NUM_NODES (NUM_USERS + NUM_ITEMS)
#define EMB_DIM 64
#define NUM_EDGES 4000000
#define BATCH 4096
#define CHUNKS 16   // 16 float4 per node row

// ---- scratch (device globals: allocation-free) ----
__device__ float4 g_h1[NUM_NODES * CHUNKS];          // 51.2 MB
__device__ float4 g_h2[NUM_NODES * CHUNKS];          // 51.2 MB (only flagged rows valid)
__device__ unsigned char g_flag[NUM_NODES];          // batch-row flags (layer2 filter)
__device__ unsigned char g_flag2[NUM_NODES];         // needed-h1-row flags (layer1 filter)
__device__ int4 g_l2[NUM_EDGES];                     // packed {row,col,val,0} layer2 edges
__device__ int4 g_l1[NUM_EDGES];                     // packed {row,col,val,0} layer1 edges
__device__ int g_c2;
__device__ int g_c1;

__device__ __forceinline__ void red_add_v4(float4* addr, float4 v) {
    asm volatile("red.global.add.v4.f32 [%0], {%1, %2, %3, %4};"
                 :: "l"(addr), "f"(v.x), "f"(v.y), "f"(v.z), "f"(v.w)
                 : "memory");
}

// ---- K0a: zero h1 + both flag arrays + counters ----
#define H1_WORDS (NUM_NODES * CHUNKS)                 // 3,200,000 float4
#define FLAG_WORDS (NUM_NODES / 16)                   // 12,500 uint4 per flag array
__global__ void k_zero(void) {
    int i = blockIdx.x * blockDim.x + threadIdx.x;
    if (i == 0) { g_c1 = 0; g_c2 = 0; }
    if (i < H1_WORDS) {
        g_h1[i] = make_float4(0.f, 0.f, 0.f, 0.f);
    } else if (i < H1_WORDS + FLAG_WORDS) {
        ((uint4*)g_flag)[i - H1_WORDS] = make_uint4(0u, 0u, 0u, 0u);
    } else if (i < H1_WORDS + 2 * FLAG_WORDS) {
        ((uint4*)g_flag2)[i - H1_WORDS - FLAG_WORDS] = make_uint4(0u, 0u, 0u, 0u);
    }
}

// ---- K0b: set batch flags (both arrays) + zero those h2 rows ----
__global__ void k_flag(const int* __restrict__ user,
                       const int* __restrict__ pos,
                       const int* __restrict__ neg) {
    int t = blockIdx.x * blockDim.x + threadIdx.x;   // 3*BATCH*16 threads
    int g = t >> 4;
    int c = t & 15;
    if (g >= 3 * BATCH) return;
    int node;
    if (g < BATCH)            node = user[g];
    else if (g < 2 * BATCH)   node = NUM_USERS + pos[g - BATCH];
    else                      node = NUM_USERS + neg[g - 2 * BATCH];
    if (c == 0) { g_flag[node] = 1; g_flag2[node] = 1; }
    g_h2[node * CHUNKS + c] = make_float4(0.f, 0.f, 0.f, 0.f);
}

// ---- K_compactA: layer-2 edge compaction + flag2[col] marking ----
// keep edge iff flag[row]; append packed record; mark its col as needed-h1.
__global__ void k_compactA(const int*   __restrict__ edge_row,
                           const int*   __restrict__ edge_col,
                           const float* __restrict__ edge_val) {
    __shared__ int s_cnt;
    __shared__ int s_base;
    __shared__ int s_warp_off[8];

    int e = blockIdx.x * blockDim.x + threadIdx.x;
    int lane = threadIdx.x & 31;
    int warp = threadIdx.x >> 5;

    if (threadIdx.x == 0) s_cnt = 0;
    __syncthreads();

    bool keep = false;
    int row = 0, col = 0; float v = 0.f;
    if (e < NUM_EDGES) {
        row = __ldg(edge_row + e);
        keep = (g_flag[row] != 0);
    }
    if (keep) {
        col = __ldg(edge_col + e);
        v   = __ldg(edge_val + e);
        g_flag2[col] = 1;
    }
    unsigned mask = __ballot_sync(0xFFFFFFFFu, keep);
    int warp_total = __popc(mask);
    int rank = __popc(mask & ((1u << lane) - 1));

    if (lane == 0 && warp_total)
        s_warp_off[warp] = atomicAdd(&s_cnt, warp_total);
    __syncthreads();
    if (threadIdx.x == 0 && s_cnt)
        s_base = atomicAdd(&g_c2, s_cnt);
    __syncthreads();

    if (keep)
        g_l2[s_base + s_warp_off[warp] + rank] = make_int4(row, col, __float_as_int(v), 0);
}

// ---- K_compactB: layer-1 edge compaction ----
// keep edge iff flag2[row] (h1[row] actually needed downstream).
__global__ void k_compactB(const int*   __restrict__ edge_row,
                           const int*   __restrict__ edge_col,
                           const float* __restrict__ edge_val) {
    __shared__ int s_cnt;
    __shared__ int s_base;
    __shared__ int s_warp_off[8];

    int e = blockIdx.x * blockDim.x + threadIdx.x;
    int lane = threadIdx.x & 31;
    int warp = threadIdx.x >> 5;

    if (threadIdx.x == 0) s_cnt = 0;
    __syncthreads();

    bool keep = false;
    int row = 0, col = 0; float v = 0.f;
    if (e < NUM_EDGES) {
        row = __ldg(edge_row + e);
        keep = (g_flag2[row] != 0);
    }
    if (keep) {
        col = __ldg(edge_col + e);
        v   = __ldg(edge_val + e);
    }
    unsigned mask = __ballot_sync(0xFFFFFFFFu, keep);
    int warp_total = __popc(mask);
    int rank = __popc(mask & ((1u << lane) - 1));

    if (lane == 0 && warp_total)
        s_warp_off[warp] = atomicAdd(&s_cnt, warp_total);
    __syncthreads();
    if (threadIdx.x == 0 && s_cnt)
        s_base = atomicAdd(&g_c1, s_cnt);
    __syncthreads();

    if (keep)
        g_l1[s_base + s_warp_off[warp] + rank] = make_int4(row, col, __float_as_int(v), 0);
}

// ---- K1: filtered SPMM layer 1 over g_l1: h1[row] += val * all_emb[col] ----
// 4 strided guarded items per thread (MLP=4). Grid covers worst case 64M items.
#define SPMM1_THREADS (16 * 1024 * 1024)     // 16M threads * 4 slots = 64M max items
__global__ void k_spmm1(const float4* __restrict__ user_emb,
                        const float4* __restrict__ item_emb) {
    long long total = (long long)g_c1 * CHUNKS;
    long long t = (long long)blockIdx.x * blockDim.x + threadIdx.x;

    #pragma unroll
    for (int k = 0; k < 4; k++) {
        long long item = t + (long long)k * SPMM1_THREADS;
        if (item < total) {
            int idx = (int)(item >> 4);
            int c = (int)(item & 15);
            int4 m = __ldg(&g_l1[idx]);             // broadcast across the 16 lanes
            float v = __int_as_float(m.z);
            const float4* src = (m.y < NUM_USERS)
                ? (user_emb + (size_t)m.y * CHUNKS)
                : (item_emb + (size_t)(m.y - NUM_USERS) * CHUNKS);
            float4 x = __ldg(src + c);
            float4 acc = make_float4(v * x.x, v * x.y, v * x.z, v * x.w);
            red_add_v4(&g_h1[(size_t)m.x * CHUNKS + c], acc);
        }
    }
}

// ---- K2: SPMM layer 2 over g_l2: h2[row] += val * h1[col] ----
__global__ void k_spmm2(void) {
    long long total = (long long)g_c2 * CHUNKS;
    long long stride = (long long)gridDim.x * blockDim.x;
    for (long long t = (long long)blockIdx.x * blockDim.x + threadIdx.x;
         t < total; t += stride) {
        int idx = (int)(t >> 4);
        int c = (int)(t & 15);
        int4 m = __ldg(&g_l2[idx]);
        float v = __int_as_float(m.z);
        float4 x = __ldg(&g_h1[(size_t)m.y * CHUNKS + c]);
        float4 acc = make_float4(v * x.x, v * x.y, v * x.z, v * x.w);
        red_add_v4(&g_h2[(size_t)m.x * CHUNKS + c], acc);
    }
}

// ---- K3: gather acc at batch nodes, dot, write scores ----
__global__ void k_score(const int* __restrict__ user,
                        const int* __restrict__ pos,
                        const int* __restrict__ neg,
                        const float2* __restrict__ user_emb2,
                        const float2* __restrict__ item_emb2,
                        float* __restrict__ out) {
    int w = (blockIdx.x * blockDim.x + threadIdx.x) >> 5;
    int lane = threadIdx.x & 31;
    if (w >= BATCH) return;
    int nu = user[w];
    int np = NUM_USERS + pos[w];
    int nn = NUM_USERS + neg[w];

    const float2* h1 = (const float2*)g_h1;
    const float2* h2 = (const float2*)g_h2;
    const int L = EMB_DIM / 2;

    float2 ue = user_emb2[(size_t)nu * L + lane];
    float2 u1 = h1[(size_t)nu * L + lane];
    float2 u2 = h2[(size_t)nu * L + lane];
    float ux = ue.x + u1.x + u2.x;
    float uy = ue.y + u1.y + u2.y;

    float2 pe = item_emb2[(size_t)(np - NUM_USERS) * L + lane];
    float2 p1 = h1[(size_t)np * L + lane];
    float2 p2 = h2[(size_t)np * L + lane];
    float px = pe.x + p1.x + p2.x;
    float py = pe.y + p1.y + p2.y;

    float2 ne = item_emb2[(size_t)(nn - NUM_USERS) * L + lane];
    float2 n1 = h1[(size_t)nn * L + lane];
    float2 n2 = h2[(size_t)nn * L + lane];
    float nx = ne.x + n1.x + n2.x;
    float ny = ne.y + n1.y + n2.y;

    float sp = ux * px + uy * py;
    float sn = ux * nx + uy * ny;
    #pragma unroll
    for (int off = 16; off > 0; off >>= 1) {
        sp += __shfl_xor_sync(0xFFFFFFFFu, sp, off);
        sn += __shfl_xor_sync(0xFFFFFFFFu, sn, off);
    }
    if (lane == 0) {
        const float inv9 = 1.0f / 9.0f;
        out[w]         = sp * inv9;
        out[BATCH + w] = sn * inv9;
    }
}

extern "C" void kernel_launch(void* const* d_in, const int* in_sizes, int n_in,
                              void* d_out, int out_size) {
    const int*   user     = (const int*)  d_in[0];
    const int*   pos      = (const int*)  d_in[1];
    const int*   neg      = (const int*)  d_in[2];
    const int*   edge_row = (const int*)  d_in[3];
    const int*   edge_col = (const int*)  d_in[4];
    const float* edge_val = (const float*)d_in[5];
    const float* user_emb = (const float*)d_in[6];
    const float* item_emb = (const float*)d_in[7];
    float* out = (float*)d_out;

    // K0a: zero h1 + flags + counters
    {
        int total = H1_WORDS + 2 * FLAG_WORDS;
        k_zero<<<(total + 255) / 256, 256>>>();
    }
    // K0b: batch flags + zero needed h2 rows
    {
        int total = 3 * BATCH * CHUNKS;
        k_flag<<<(total + 255) / 256, 256>>>(user, pos, neg);
    }
    // Compact layer-2 edges (flag[row]) + mark needed h1 rows (flag2[col])
    k_compactA<<<(NUM_EDGES + 255) / 256, 256>>>(edge_row, edge_col, edge_val);
    // Compact layer-1 edges (flag2[row])
    k_compactB<<<(NUM_EDGES + 255) / 256, 256>>>(edge_row, edge_col, edge_val);
    // SPMM layer 1 over compacted list (ILP=4)
    k_spmm1<<<SPMM1_THREADS / 256, 256>>>((const float4*)user_emb,
                                          (const float4*)item_emb);
    // SPMM layer 2 over compacted list
    k_spmm2<<<8192, 256>>>();
    // Scores
    {
        int threads = 256;
        int blocks = (BATCH * 32 + threads - 1) / threads;
        k_score<<<blocks, threads>>>(user, pos, neg,
                                     (const float2*)user_emb, (const float2*)item_emb,
                                     out);
    }
}

// round 7
// speedup vs baseline: 2.1066x; 1.0365x over previous
#include <cuda_runtime.h>
#include <cuda_bf16.h>
#include <cuda_fp16.h>
#include <cstdint>

#define NUM_USERS 100000
#define NUM_ITEMS 100000
#define NUM_NODES (NUM_USERS + NUM_ITEMS)
#define EMB_DIM 64
#define NUM_EDGES 4000000
#define BATCH 4096
#define CHUNKS 16   // 16 float4 per node row

// ---- scratch (device globals: allocation-free) ----
__device__ float4 g_h1[NUM_NODES * CHUNKS];          // 51.2 MB
__device__ float4 g_h2[NUM_NODES * CHUNKS];          // 51.2 MB (only flagged rows valid)
__device__ __half  g_embh[NUM_NODES * EMB_DIM];      // 25.6 MB fp16 copy of all_emb
__device__ unsigned char g_flag[NUM_NODES];          // batch-row flags (layer2 filter)
__device__ unsigned char g_flag2[NUM_NODES];         // needed-h1-row flags (layer1 filter)
__device__ int4 g_l2[NUM_EDGES];                     // packed {row,col,val,0} layer2 edges
__device__ int4 g_l1[NUM_EDGES];                     // packed {row,col,val,0} layer1 edges
__device__ int g_c2;
__device__ int g_c1;

__device__ __forceinline__ void red_add_v4(float4* addr, float4 v) {
    asm volatile("red.global.add.v4.f32 [%0], {%1, %2, %3, %4};"
                 :: "l"(addr), "f"(v.x), "f"(v.y), "f"(v.z), "f"(v.w)
                 : "memory");
}

// ---- K0a: zero h1 + both flag arrays + counters ----
#define H1_WORDS (NUM_NODES * CHUNKS)                 // 3,200,000 float4
#define FLAG_WORDS (NUM_NODES / 16)                   // 12,500 uint4 per flag array
__global__ void k_zero(void) {
    int i = blockIdx.x * blockDim.x + threadIdx.x;
    if (i == 0) { g_c1 = 0; g_c2 = 0; }
    if (i < H1_WORDS) {
        g_h1[i] = make_float4(0.f, 0.f, 0.f, 0.f);
    } else if (i < H1_WORDS + FLAG_WORDS) {
        ((uint4*)g_flag)[i - H1_WORDS] = make_uint4(0u, 0u, 0u, 0u);
    } else if (i < H1_WORDS + 2 * FLAG_WORDS) {
        ((uint4*)g_flag2)[i - H1_WORDS - FLAG_WORDS] = make_uint4(0u, 0u, 0u, 0u);
    }
}

// ---- K0b: set batch flags (both arrays) + zero those h2 rows ----
__global__ void k_flag(const int* __restrict__ user,
                       const int* __restrict__ pos,
                       const int* __restrict__ neg) {
    int t = blockIdx.x * blockDim.x + threadIdx.x;   // 3*BATCH*16 threads
    int g = t >> 4;
    int c = t & 15;
    if (g >= 3 * BATCH) return;
    int node;
    if (g < BATCH)            node = user[g];
    else if (g < 2 * BATCH)   node = NUM_USERS + pos[g - BATCH];
    else                      node = NUM_USERS + neg[g - 2 * BATCH];
    if (c == 0) { g_flag[node] = 1; g_flag2[node] = 1; }
    g_h2[node * CHUNKS + c] = make_float4(0.f, 0.f, 0.f, 0.f);
}

// ---- K0c: convert all_emb to fp16 (8 floats per thread) ----
#define CVT_GROUPS (NUM_NODES * EMB_DIM / 8)          // 1.6M
#define CVT_USER_GROUPS (NUM_USERS * EMB_DIM / 8)     // 800K
__global__ void k_cvt(const float4* __restrict__ user_emb,
                      const float4* __restrict__ item_emb) {
    int g = blockIdx.x * blockDim.x + threadIdx.x;
    if (g >= CVT_GROUPS) return;
    const float4* src = (g < CVT_USER_GROUPS)
        ? (user_emb + (size_t)g * 2)
        : (item_emb + (size_t)(g - CVT_USER_GROUPS) * 2);
    float4 a = __ldg(src);
    float4 b = __ldg(src + 1);
    __half2 h0 = __floats2half2_rn(a.x, a.y);
    __half2 h1 = __floats2half2_rn(a.z, a.w);
    __half2 h2 = __floats2half2_rn(b.x, b.y);
    __half2 h3 = __floats2half2_rn(b.z, b.w);
    uint4 o;
    o.x = *reinterpret_cast<unsigned*>(&h0);
    o.y = *reinterpret_cast<unsigned*>(&h1);
    o.z = *reinterpret_cast<unsigned*>(&h2);
    o.w = *reinterpret_cast<unsigned*>(&h3);
    ((uint4*)g_embh)[g] = o;
}

// ---- compaction (4 edges/thread, warp-prefix + block-aggregated atomic) ----
#define COMPACT_THREADS (NUM_EDGES / 4)               // 1,000,000

__device__ __forceinline__ void compact_body(
    const int4*   __restrict__ rows4,
    const int4*   __restrict__ cols4,
    const float4* __restrict__ vals4,
    const unsigned char* __restrict__ flag,
    int4* __restrict__ out_list,
    int* counter,
    bool mark_flag2)
{
    __shared__ int s_cnt;
    __shared__ int s_base;
    __shared__ int s_warp_off[8];

    int t = blockIdx.x * blockDim.x + threadIdx.x;
    int lane = threadIdx.x & 31;
    int warp = threadIdx.x >> 5;
    if (threadIdx.x == 0) s_cnt = 0;
    __syncthreads();

    int4 r = make_int4(0, 0, 0, 0), cc = make_int4(0, 0, 0, 0);
    float4 vv = make_float4(0.f, 0.f, 0.f, 0.f);
    bool k0 = false, k1 = false, k2 = false, k3 = false;
    if (t < COMPACT_THREADS) {
        r  = __ldg(rows4 + t);
        cc = __ldg(cols4 + t);
        vv = __ldg(vals4 + t);
        k0 = flag[r.x] != 0;
        k1 = flag[r.y] != 0;
        k2 = flag[r.z] != 0;
        k3 = flag[r.w] != 0;
        if (mark_flag2) {
            if (k0) g_flag2[cc.x] = 1;
            if (k1) g_flag2[cc.y] = 1;
            if (k2) g_flag2[cc.z] = 1;
            if (k3) g_flag2[cc.w] = 1;
        }
    }
    int n = (int)k0 + (int)k1 + (int)k2 + (int)k3;
    int pre = n;
    #pragma unroll
    for (int o = 1; o < 32; o <<= 1) {
        int x = __shfl_up_sync(0xFFFFFFFFu, pre, o);
        if (lane >= o) pre += x;
    }
    int excl = pre - n;
    int wtot = __shfl_sync(0xFFFFFFFFu, pre, 31);

    if (lane == 31) s_warp_off[warp] = atomicAdd(&s_cnt, wtot);
    __syncthreads();
    if (threadIdx.x == 0) s_base = atomicAdd(counter, s_cnt);
    __syncthreads();

    int p = s_base + s_warp_off[warp] + excl;
    if (k0) out_list[p++] = make_int4(r.x, cc.x, __float_as_int(vv.x), 0);
    if (k1) out_list[p++] = make_int4(r.y, cc.y, __float_as_int(vv.y), 0);
    if (k2) out_list[p++] = make_int4(r.z, cc.z, __float_as_int(vv.z), 0);
    if (k3) out_list[p++] = make_int4(r.w, cc.w, __float_as_int(vv.w), 0);
}

__global__ void k_compactA(const int* __restrict__ edge_row,
                           const int* __restrict__ edge_col,
                           const float* __restrict__ edge_val) {
    compact_body((const int4*)edge_row, (const int4*)edge_col,
                 (const float4*)edge_val, g_flag, g_l2, &g_c2, true);
}

__global__ void k_compactB(const int* __restrict__ edge_row,
                           const int* __restrict__ edge_col,
                           const float* __restrict__ edge_val) {
    compact_body((const int4*)edge_row, (const int4*)edge_col,
                 (const float4*)edge_val, g_flag2, g_l1, &g_c1, false);
}

// ---- K1: filtered SPMM layer 1 over g_l1: h1[row] += val * embh[col] ----
// fp16 gather (8B per lane), fp32 red. 4 strided guarded items per thread.
#define SPMM1_THREADS (16 * 1024 * 1024)
__global__ void k_spmm1(void) {
    long long total = (long long)g_c1 * CHUNKS;
    long long t = (long long)blockIdx.x * blockDim.x + threadIdx.x;

    #pragma unroll
    for (int k = 0; k < 4; k++) {
        long long item = t + (long long)k * SPMM1_THREADS;
        if (item < total) {
            int idx = (int)(item >> 4);
            int c = (int)(item & 15);
            int4 m = __ldg(&g_l1[idx]);             // broadcast across 16 lanes
            float v = __int_as_float(m.z);
            const __half* src = g_embh + ((size_t)m.y << 6) + (c << 2);
            uint2 u = __ldg((const uint2*)src);
            __half2 ha = *reinterpret_cast<__half2*>(&u.x);
            __half2 hb = *reinterpret_cast<__half2*>(&u.y);
            float2 fa = __half22float2(ha);
            float2 fb = __half22float2(hb);
            float4 acc = make_float4(v * fa.x, v * fa.y, v * fb.x, v * fb.y);
            red_add_v4(&g_h1[(size_t)m.x * CHUNKS + c], acc);
        }
    }
}

// ---- K2: SPMM layer 2 over g_l2: h2[row] += val * h1[col] ----
__global__ void k_spmm2(void) {
    long long total = (long long)g_c2 * CHUNKS;
    long long stride = (long long)gridDim.x * blockDim.x;
    for (long long t = (long long)blockIdx.x * blockDim.x + threadIdx.x;
         t < total; t += stride) {
        int idx = (int)(t >> 4);
        int c = (int)(t & 15);
        int4 m = __ldg(&g_l2[idx]);
        float v = __int_as_float(m.z);
        float4 x = __ldg(&g_h1[(size_t)m.y * CHUNKS + c]);
        float4 acc = make_float4(v * x.x, v * x.y, v * x.z, v * x.w);
        red_add_v4(&g_h2[(size_t)m.x * CHUNKS + c], acc);
    }
}

// ---- K3: gather acc at batch nodes, dot, write scores ----
__global__ void k_score(const int* __restrict__ user,
                        const int* __restrict__ pos,
                        const int* __restrict__ neg,
                        const float2* __restrict__ user_emb2,
                        const float2* __restrict__ item_emb2,
                        float* __restrict__ out) {
    int w = (blockIdx.x * blockDim.x + threadIdx.x) >> 5;
    int lane = threadIdx.x & 31;
    if (w >= BATCH) return;
    int nu = user[w];
    int np = NUM_USERS + pos[w];
    int nn = NUM_USERS + neg[w];

    const float2* h1 = (const float2*)g_h1;
    const float2* h2 = (const float2*)g_h2;
    const int L = EMB_DIM / 2;

    float2 ue = user_emb2[(size_t)nu * L + lane];
    float2 u1 = h1[(size_t)nu * L + lane];
    float2 u2 = h2[(size_t)nu * L + lane];
    float ux = ue.x + u1.x + u2.x;
    float uy = ue.y + u1.y + u2.y;

    float2 pe = item_emb2[(size_t)(np - NUM_USERS) * L + lane];
    float2 p1 = h1[(size_t)np * L + lane];
    float2 p2 = h2[(size_t)np * L + lane];
    float px = pe.x + p1.x + p2.x;
    float py = pe.y + p1.y + p2.y;

    float2 ne = item_emb2[(size_t)(nn - NUM_USERS) * L + lane];
    float2 n1 = h1[(size_t)nn * L + lane];
    float2 n2 = h2[(size_t)nn * L + lane];
    float nx = ne.x + n1.x + n2.x;
    float ny = ne.y + n1.y + n2.y;

    float sp = ux * px + uy * py;
    float sn = ux * nx + uy * ny;
    #pragma unroll
    for (int off = 16; off > 0; off >>= 1) {
        sp += __shfl_xor_sync(0xFFFFFFFFu, sp, off);
        sn += __shfl_xor_sync(0xFFFFFFFFu, sn, off);
    }
    if (lane == 0) {
        const float inv9 = 1.0f / 9.0f;
        out[w]         = sp * inv9;
        out[BATCH + w] = sn * inv9;
    }
}

extern "C" void kernel_launch(void* const* d_in, const int* in_sizes, int n_in,
                              void* d_out, int out_size) {
    const int*   user     = (const int*)  d_in[0];
    const int*   pos      = (const int*)  d_in[1];
    const int*   neg      = (const int*)  d_in[2];
    const int*   edge_row = (const int*)  d_in[3];
    const int*   edge_col = (const int*)  d_in[4];
    const float* edge_val = (const float*)d_in[5];
    const float* user_emb = (const float*)d_in[6];
    const float* item_emb = (const float*)d_in[7];
    float* out = (float*)d_out;

    // K0a: zero h1 + flags + counters
    {
        int total = H1_WORDS + 2 * FLAG_WORDS;
        k_zero<<<(total + 255) / 256, 256>>>();
    }
    // K0b: batch flags + zero needed h2 rows
    {
        int total = 3 * BATCH * CHUNKS;
        k_flag<<<(total + 255) / 256, 256>>>(user, pos, neg);
    }
    // K0c: fp16 embedding copy
    k_cvt<<<(CVT_GROUPS + 255) / 256, 256>>>((const float4*)user_emb,
                                             (const float4*)item_emb);
    // Compact layer-2 edges (flag[row]) + mark needed h1 rows (flag2[col])
    k_compactA<<<(COMPACT_THREADS + 255) / 256, 256>>>(edge_row, edge_col, edge_val);
    // Compact layer-1 edges (flag2[row])
    k_compactB<<<(COMPACT_THREADS + 255) / 256, 256>>>(edge_row, edge_col, edge_val);
    // SPMM layer 1 over compacted list (fp16 gather, ILP=4)
    k_spmm1<<<SPMM1_THREADS / 256, 256>>>();
    // SPMM layer 2 over compacted list
    k_spmm2<<<8192, 256>>>();
    // Scores
    {
        int threads = 256;
        int blocks = (BATCH * 32 + threads - 1) / threads;
        k_score<<<blocks, threads>>>(user, pos, neg,
                                     (const float2*)user_emb, (const float2*)item_emb,
                                     out);
    }
}

// round 9
// speedup vs baseline: 3.1752x; 1.5073x over previous
#include <cuda_runtime.h>
#include <cuda_bf16.h>
#include <cuda_fp16.h>
#include <cstdint>

#define NUM_USERS 100000
#define NUM_ITEMS 100000
#define NUM_NODES (NUM_USERS + NUM_ITEMS)
#define EMB_DIM 64
#define NUM_EDGES 4000000
#define BATCH 4096
#define CHUNKS 16   // 16 float4 per node row (fp32 arrays)

// ---- scratch (device globals: allocation-free) ----
__device__ uint4  g_h1h[NUM_NODES * 8];              // fp16 h1: 64 halves/node = 25.6 MB
__device__ float4 g_h2[NUM_NODES * CHUNKS];          // fp32 h2 (only flagged rows valid)
__device__ uint4  g_embh[NUM_NODES * 8];             // fp16 copy of all_emb, 25.6 MB
__device__ unsigned char g_flag[NUM_NODES];          // batch-row flags (layer2 filter)
__device__ unsigned char g_flag2[NUM_NODES];         // needed-h1-row flags (layer1 filter)
__device__ int4 g_l2[NUM_EDGES];                     // packed {row,col,val,0} layer2 edges
__device__ int4 g_l1[NUM_EDGES];                     // packed {row,col,val,0} layer1 edges
__device__ int g_c2;
__device__ int g_c1;

__device__ __forceinline__ void red_add_v4_f32(float4* addr, float4 v) {
    asm volatile("red.global.add.v4.f32 [%0], {%1, %2, %3, %4};"
                 :: "l"(addr), "f"(v.x), "f"(v.y), "f"(v.z), "f"(v.w)
                 : "memory");
}

// 16B vectorized fp16 reduction: adds 8 halves (4x half2) atomically.
__device__ __forceinline__ void red_add_v4_f16x2(uint4* addr, uint4 v) {
    asm volatile("red.global.add.noftz.v4.f16x2 [%0], {%1, %2, %3, %4};"
                 :: "l"(addr), "r"(v.x), "r"(v.y), "r"(v.z), "r"(v.w)
                 : "memory");
}

// ---- K0a: zero h1 (fp16) + both flag arrays + counters ----
#define H1H_WORDS (NUM_NODES * 8)                     // 1.6M uint4
#define FLAG_WORDS (NUM_NODES / 16)                   // 12,500 uint4 per flag array
__global__ void k_zero(void) {
    int i = blockIdx.x * blockDim.x + threadIdx.x;
    if (i == 0) { g_c1 = 0; g_c2 = 0; }
    if (i < H1H_WORDS) {
        g_h1h[i] = make_uint4(0u, 0u, 0u, 0u);
    } else if (i < H1H_WORDS + FLAG_WORDS) {
        ((uint4*)g_flag)[i - H1H_WORDS] = make_uint4(0u, 0u, 0u, 0u);
    } else if (i < H1H_WORDS + 2 * FLAG_WORDS) {
        ((uint4*)g_flag2)[i - H1H_WORDS - FLAG_WORDS] = make_uint4(0u, 0u, 0u, 0u);
    }
}

// ---- K0b: set batch flags (both arrays) + zero those h2 rows ----
__global__ void k_flag(const int* __restrict__ user,
                       const int* __restrict__ pos,
                       const int* __restrict__ neg) {
    int t = blockIdx.x * blockDim.x + threadIdx.x;   // 3*BATCH*16 threads
    int g = t >> 4;
    int c = t & 15;
    if (g >= 3 * BATCH) return;
    int node;
    if (g < BATCH)            node = user[g];
    else if (g < 2 * BATCH)   node = NUM_USERS + pos[g - BATCH];
    else                      node = NUM_USERS + neg[g - 2 * BATCH];
    if (c == 0) { g_flag[node] = 1; g_flag2[node] = 1; }
    g_h2[node * CHUNKS + c] = make_float4(0.f, 0.f, 0.f, 0.f);
}

// ---- K0c: convert all_emb to fp16 (8 floats per thread) ----
#define CVT_GROUPS (NUM_NODES * EMB_DIM / 8)          // 1.6M
#define CVT_USER_GROUPS (NUM_USERS * EMB_DIM / 8)     // 800K
__global__ void k_cvt(const float4* __restrict__ user_emb,
                      const float4* __restrict__ item_emb) {
    int g = blockIdx.x * blockDim.x + threadIdx.x;
    if (g >= CVT_GROUPS) return;
    const float4* src = (g < CVT_USER_GROUPS)
        ? (user_emb + (size_t)g * 2)
        : (item_emb + (size_t)(g - CVT_USER_GROUPS) * 2);
    float4 a = __ldg(src);
    float4 b = __ldg(src + 1);
    __half2 h0 = __floats2half2_rn(a.x, a.y);
    __half2 h1 = __floats2half2_rn(a.z, a.w);
    __half2 h2 = __floats2half2_rn(b.x, b.y);
    __half2 h3 = __floats2half2_rn(b.z, b.w);
    uint4 o;
    o.x = *reinterpret_cast<unsigned*>(&h0);
    o.y = *reinterpret_cast<unsigned*>(&h1);
    o.z = *reinterpret_cast<unsigned*>(&h2);
    o.w = *reinterpret_cast<unsigned*>(&h3);
    g_embh[g] = o;
}

// ---- compaction (4 edges/thread, warp-prefix + block-aggregated atomic) ----
#define COMPACT_THREADS (NUM_EDGES / 4)               // 1,000,000

__device__ __forceinline__ void compact_body(
    const int4*   __restrict__ rows4,
    const int4*   __restrict__ cols4,
    const float4* __restrict__ vals4,
    const unsigned char* __restrict__ flag,
    int4* __restrict__ out_list,
    int* counter,
    bool mark_flag2)
{
    __shared__ int s_cnt;
    __shared__ int s_base;
    __shared__ int s_warp_off[8];

    int t = blockIdx.x * blockDim.x + threadIdx.x;
    int lane = threadIdx.x & 31;
    int warp = threadIdx.x >> 5;
    if (threadIdx.x == 0) s_cnt = 0;
    __syncthreads();

    int4 r = make_int4(0, 0, 0, 0), cc = make_int4(0, 0, 0, 0);
    float4 vv = make_float4(0.f, 0.f, 0.f, 0.f);
    bool k0 = false, k1 = false, k2 = false, k3 = false;
    if (t < COMPACT_THREADS) {
        r  = __ldg(rows4 + t);
        cc = __ldg(cols4 + t);
        vv = __ldg(vals4 + t);
        k0 = flag[r.x] != 0;
        k1 = flag[r.y] != 0;
        k2 = flag[r.z] != 0;
        k3 = flag[r.w] != 0;
        if (mark_flag2) {
            if (k0) g_flag2[cc.x] = 1;
            if (k1) g_flag2[cc.y] = 1;
            if (k2) g_flag2[cc.z] = 1;
            if (k3) g_flag2[cc.w] = 1;
        }
    }
    int n = (int)k0 + (int)k1 + (int)k2 + (int)k3;
    int pre = n;
    #pragma unroll
    for (int o = 1; o < 32; o <<= 1) {
        int x = __shfl_up_sync(0xFFFFFFFFu, pre, o);
        if (lane >= o) pre += x;
    }
    int excl = pre - n;
    int wtot = __shfl_sync(0xFFFFFFFFu, pre, 31);

    if (lane == 31) s_warp_off[warp] = atomicAdd(&s_cnt, wtot);
    __syncthreads();
    if (threadIdx.x == 0) s_base = atomicAdd(counter, s_cnt);
    __syncthreads();

    int p = s_base + s_warp_off[warp] + excl;
    if (k0) out_list[p++] = make_int4(r.x, cc.x, __float_as_int(vv.x), 0);
    if (k1) out_list[p++] = make_int4(r.y, cc.y, __float_as_int(vv.y), 0);
    if (k2) out_list[p++] = make_int4(r.z, cc.z, __float_as_int(vv.z), 0);
    if (k3) out_list[p++] = make_int4(r.w, cc.w, __float_as_int(vv.w), 0);
}

__global__ void k_compactA(const int* __restrict__ edge_row,
                           const int* __restrict__ edge_col,
                           const float* __restrict__ edge_val) {
    compact_body((const int4*)edge_row, (const int4*)edge_col,
                 (const float4*)edge_val, g_flag, g_l2, &g_c2, true);
}

__global__ void k_compactB(const int* __restrict__ edge_row,
                           const int* __restrict__ edge_col,
                           const float* __restrict__ edge_val) {
    compact_body((const int4*)edge_row, (const int4*)edge_col,
                 (const float4*)edge_val, g_flag2, g_l1, &g_c1, false);
}

// ---- K1: filtered SPMM layer 1: h1h[row] += val * embh[col] (all fp16 halves) ----
// 8 lanes per edge, 16B per lane (8 halves). ILP=4 strided guarded items.
#define SPMM1_THREADS (8 * 1024 * 1024)   // * 4 slots = 32M max items (4M edges * 8)
__global__ void k_spmm1(void) {
    long long total = (long long)g_c1 * 8;
    long long t = (long long)blockIdx.x * blockDim.x + threadIdx.x;

    #pragma unroll
    for (int k = 0; k < 4; k++) {
        long long item = t + (long long)k * SPMM1_THREADS;
        if (item < total) {
            int idx = (int)(item >> 3);
            int c = (int)(item & 7);
            int4 m = __ldg(&g_l1[idx]);             // broadcast across 8 lanes
            float v = __int_as_float(m.z);
            __half2 vh = __float2half2_rn(v);
            uint4 u = __ldg(&g_embh[((size_t)m.y << 3) + c]);
            __half2 a = *reinterpret_cast<__half2*>(&u.x);
            __half2 b = *reinterpret_cast<__half2*>(&u.y);
            __half2 d = *reinterpret_cast<__half2*>(&u.z);
            __half2 e = *reinterpret_cast<__half2*>(&u.w);
            a = __hmul2(a, vh);
            b = __hmul2(b, vh);
            d = __hmul2(d, vh);
            e = __hmul2(e, vh);
            uint4 o;
            o.x = *reinterpret_cast<unsigned*>(&a);
            o.y = *reinterpret_cast<unsigned*>(&b);
            o.z = *reinterpret_cast<unsigned*>(&d);
            o.w = *reinterpret_cast<unsigned*>(&e);
            red_add_v4_f16x2(&g_h1h[((size_t)m.x << 3) + c], o);
        }
    }
}

// ---- K2: SPMM layer 2: h2[row] += val * h1h[col] (fp16 gather, fp32 red) ----
__global__ void k_spmm2(void) {
    long long total = (long long)g_c2 * CHUNKS;
    long long stride = (long long)gridDim.x * blockDim.x;
    const uint2* h1 = (const uint2*)g_h1h;   // 4 halves per uint2
    for (long long t = (long long)blockIdx.x * blockDim.x + threadIdx.x;
         t < total; t += stride) {
        int idx = (int)(t >> 4);
        int c = (int)(t & 15);
        int4 m = __ldg(&g_l2[idx]);
        float v = __int_as_float(m.z);
        uint2 u = __ldg(&h1[((size_t)m.y << 4) + c]);
        __half2 ha = *reinterpret_cast<__half2*>(&u.x);
        __half2 hb = *reinterpret_cast<__half2*>(&u.y);
        float2 fa = __half22float2(ha);
        float2 fb = __half22float2(hb);
        float4 acc = make_float4(v * fa.x, v * fa.y, v * fb.x, v * fb.y);
        red_add_v4_f32(&g_h2[(size_t)m.x * CHUNKS + c], acc);
    }
}

// ---- K3: gather acc at batch nodes, dot, write scores ----
__global__ void k_score(const int* __restrict__ user,
                        const int* __restrict__ pos,
                        const int* __restrict__ neg,
                        const float2* __restrict__ user_emb2,
                        const float2* __restrict__ item_emb2,
                        float* __restrict__ out) {
    int w = (blockIdx.x * blockDim.x + threadIdx.x) >> 5;
    int lane = threadIdx.x & 31;
    if (w >= BATCH) return;
    int nu = user[w];
    int np = NUM_USERS + pos[w];
    int nn = NUM_USERS + neg[w];

    const unsigned* h1u = (const unsigned*)g_h1h;   // 2 halves per word
    const float2* h2 = (const float2*)g_h2;
    const int L = EMB_DIM / 2;

    unsigned w1u = __ldg(&h1u[(size_t)nu * L + lane]);
    __half2 hu = *reinterpret_cast<__half2*>(&w1u);
    float2 u1 = __half22float2(hu);
    float2 ue = user_emb2[(size_t)nu * L + lane];
    float2 u2 = h2[(size_t)nu * L + lane];
    float ux = ue.x + u1.x + u2.x;
    float uy = ue.y + u1.y + u2.y;

    unsigned w1p = __ldg(&h1u[(size_t)np * L + lane]);
    __half2 hp = *reinterpret_cast<__half2*>(&w1p);
    float2 p1 = __half22float2(hp);
    float2 pe = item_emb2[(size_t)(np - NUM_USERS) * L + lane];
    float2 p2 = h2[(size_t)np * L + lane];
    float px = pe.x + p1.x + p2.x;
    float py = pe.y + p1.y + p2.y;

    unsigned w1n = __ldg(&h1u[(size_t)nn * L + lane]);
    __half2 hn = *reinterpret_cast<__half2*>(&w1n);
    float2 n1 = __half22float2(hn);
    float2 ne = item_emb2[(size_t)(nn - NUM_USERS) * L + lane];
    float2 n2 = h2[(size_t)nn * L + lane];
    float nx = ne.x + n1.x + n2.x;
    float ny = ne.y + n1.y + n2.y;

    float sp = ux * px + uy * py;
    float sn = ux * nx + uy * ny;
    #pragma unroll
    for (int off = 16; off > 0; off >>= 1) {
        sp += __shfl_xor_sync(0xFFFFFFFFu, sp, off);
        sn += __shfl_xor_sync(0xFFFFFFFFu, sn, off);
    }
    if (lane == 0) {
        const float inv9 = 1.0f / 9.0f;
        out[w]         = sp * inv9;
        out[BATCH + w] = sn * inv9;
    }
}

extern "C" void kernel_launch(void* const* d_in, const int* in_sizes, int n_in,
                              void* d_out, int out_size) {
    const int*   user     = (const int*)  d_in[0];
    const int*   pos      = (const int*)  d_in[1];
    const int*   neg      = (const int*)  d_in[2];
    const int*   edge_row = (const int*)  d_in[3];
    const int*   edge_col = (const int*)  d_in[4];
    const float* edge_val = (const float*)d_in[5];
    const float* user_emb = (const float*)d_in[6];
    const float* item_emb = (const float*)d_in[7];
    float* out = (float*)d_out;

    // K0a: zero h1 (fp16) + flags + counters
    {
        int total = H1H_WORDS + 2 * FLAG_WORDS;
        k_zero<<<(total + 255) / 256, 256>>>();
    }
    // K0b: batch flags + zero needed h2 rows
    {
        int total = 3 * BATCH * CHUNKS;
        k_flag<<<(total + 255) / 256, 256>>>(user, pos, neg);
    }
    // K0c: fp16 embedding copy
    k_cvt<<<(CVT_GROUPS + 255) / 256, 256>>>((const float4*)user_emb,
                                             (const float4*)item_emb);
    // Compact layer-2 edges (flag[row]) + mark needed h1 rows (flag2[col])
    k_compactA<<<(COMPACT_THREADS + 255) / 256, 256>>>(edge_row, edge_col, edge_val);
    // Compact layer-1 edges (flag2[row])
    k_compactB<<<(COMPACT_THREADS + 255) / 256, 256>>>(edge_row, edge_col, edge_val);
    // SPMM layer 1 (fp16 gather + fp16 vector red, ILP=4)
    k_spmm1<<<SPMM1_THREADS / 256, 256>>>();
    // SPMM layer 2 (fp16 gather, fp32 red)
    k_spmm2<<<8192, 256>>>();
    // Scores
    {
        int threads = 256;
        int blocks = (BATCH * 32 + threads - 1) / threads;
        k_score<<<blocks, threads>>>(user, pos, neg,
                                     (const float2*)user_emb, (const float2*)item_emb,
                                     out);
    }
}